// round 1
// baseline (speedup 1.0000x reference)
#include <cuda_runtime.h>
#include <cuda_bf16.h>
#include <math.h>

// Problem constants
#define B 64
#define T 128
#define I 1024
#define H 4096
#define NNZ_IH 262144
#define NNZ_HH 1048576
#define LN_EPS 1e-5f

// ---------------- device scratch (static, no allocations) ----------------
__device__ __align__(16) float g_xT[(size_t)T * I * B];   // 32 MB, (t, i, b)
__device__ __align__(16) int   g_ih_col[NNZ_IH];
__device__ __align__(16) float g_ih_val[NNZ_IH];
__device__ __align__(16) int   g_hh_col[NNZ_HH];
__device__ __align__(16) float g_hh_val[NNZ_HH];
__device__ int   g_ih_ptr[H + 1];
__device__ int   g_hh_ptr[H + 1];
__device__ int   g_ih_ofs[H];
__device__ int   g_hh_ofs[H];
__device__ __align__(16) float g_h[H * B];     // (r, b), b contiguous
__device__ __align__(16) float g_act[H * B];   // tanh(pre), (r, b)

// ---------------- preprocessing ----------------

__global__ void k_init() {
    int idx = blockIdx.x * blockDim.x + threadIdx.x;
    int stride = gridDim.x * blockDim.x;
    for (int j = idx; j < H; j += stride) { g_ih_ofs[j] = 0; g_hh_ofs[j] = 0; }
    for (int j = idx; j < H * B; j += stride) g_h[j] = 0.0f;
}

__global__ void k_hist(const int* __restrict__ ih_rows, const int* __restrict__ hh_rows) {
    int idx = blockIdx.x * blockDim.x + threadIdx.x;
    int stride = gridDim.x * blockDim.x;
    for (int e = idx; e < NNZ_HH; e += stride) {
        atomicAdd(&g_hh_ofs[hh_rows[e]], 1);
        if (e < NNZ_IH) atomicAdd(&g_ih_ofs[ih_rows[e]], 1);
    }
}

// single block, 1024 threads: exclusive scan of both 4096-entry histograms
__global__ void k_scan() {
    __shared__ int s[H];
    __shared__ int aux[1024];
    int tid = threadIdx.x;
    for (int pass = 0; pass < 2; pass++) {
        int* cnt = pass ? g_hh_ofs : g_ih_ofs;
        int* ptr = pass ? g_hh_ptr : g_ih_ptr;
        for (int j = tid; j < H; j += 1024) s[j] = cnt[j];
        __syncthreads();
        int base = tid * 4;
        int a0 = s[base], a1 = s[base + 1], a2 = s[base + 2], a3 = s[base + 3];
        int tsum = a0 + a1 + a2 + a3;
        aux[tid] = tsum;
        __syncthreads();
        for (int off = 1; off < 1024; off <<= 1) {
            int v = (tid >= off) ? aux[tid - off] : 0;
            __syncthreads();
            aux[tid] += v;
            __syncthreads();
        }
        int excl = aux[tid] - tsum;
        int p0 = excl, p1 = excl + a0, p2 = excl + a0 + a1, p3 = excl + a0 + a1 + a2;
        ptr[base] = p0; ptr[base + 1] = p1; ptr[base + 2] = p2; ptr[base + 3] = p3;
        cnt[base] = p0; cnt[base + 1] = p1; cnt[base + 2] = p2; cnt[base + 3] = p3;
        if (tid == 1023) ptr[H] = aux[1023];
        __syncthreads();
    }
}

__global__ void k_scatter(const int* __restrict__ ih_rows, const int* __restrict__ ih_cols,
                          const float* __restrict__ ih_vals,
                          const int* __restrict__ hh_rows, const int* __restrict__ hh_cols,
                          const float* __restrict__ hh_vals) {
    int idx = blockIdx.x * blockDim.x + threadIdx.x;
    int stride = gridDim.x * blockDim.x;
    for (int e = idx; e < NNZ_HH; e += stride) {
        int r = hh_rows[e];
        int p = atomicAdd(&g_hh_ofs[r], 1);
        g_hh_col[p] = hh_cols[e];
        g_hh_val[p] = hh_vals[e];
        if (e < NNZ_IH) {
            int r2 = ih_rows[e];
            int p2 = atomicAdd(&g_ih_ofs[r2], 1);
            g_ih_col[p2] = ih_cols[e];
            g_ih_val[p2] = ih_vals[e];
        }
    }
}

// x (B, T, I) -> xT (T, I, B); index by output for coalesced writes
__global__ void k_transpose(const float* __restrict__ x) {
    size_t idx = (size_t)blockIdx.x * blockDim.x + threadIdx.x;
    size_t stride = (size_t)gridDim.x * blockDim.x;
    const size_t total = (size_t)T * I * B;
    for (size_t j = idx; j < total; j += stride) {
        int b = (int)(j % B);
        int i = (int)((j / B) % I);
        int t = (int)(j / ((size_t)B * I));
        g_xT[j] = x[(size_t)b * T * I + (size_t)t * I + i];
    }
}

// ---------------- per-step kernels ----------------

// warp per row; lanes cover 64 batch columns as float2
__global__ void __launch_bounds__(256) k_spmm(const float* __restrict__ b_ih,
                                              const float* __restrict__ b_hh, int t) {
    int warp = blockIdx.x * 8 + (threadIdx.x >> 5);
    int lane = threadIdx.x & 31;
    int row = warp;                 // grid sized to exactly H warps

    float bias = b_ih[row] + b_hh[row];
    float2 acc; acc.x = bias; acc.y = bias;

    const float2* __restrict__ xsrc =
        reinterpret_cast<const float2*>(g_xT + (size_t)t * I * B);
    const float2* __restrict__ hsrc = reinterpret_cast<const float2*>(g_h);

    // ---- ih pass ----
    {
        int start = g_ih_ptr[row], end = g_ih_ptr[row + 1];
        for (int e0 = start; e0 < end; e0 += 32) {
            int e = e0 + lane;
            int c = 0; float v = 0.0f;
            if (e < end) { c = g_ih_col[e]; v = g_ih_val[e]; }
            int n = end - e0; if (n > 32) n = 32;
            if (n == 32) {
                #pragma unroll
                for (int k = 0; k < 32; k++) {
                    int   cc = __shfl_sync(0xffffffffu, c, k);
                    float vv = __shfl_sync(0xffffffffu, v, k);
                    float2 d = xsrc[cc * 32 + lane];
                    acc.x += vv * d.x; acc.y += vv * d.y;
                }
            } else {
                for (int k = 0; k < n; k++) {
                    int   cc = __shfl_sync(0xffffffffu, c, k);
                    float vv = __shfl_sync(0xffffffffu, v, k);
                    float2 d = xsrc[cc * 32 + lane];
                    acc.x += vv * d.x; acc.y += vv * d.y;
                }
            }
        }
    }
    // ---- hh pass ----
    {
        int start = g_hh_ptr[row], end = g_hh_ptr[row + 1];
        for (int e0 = start; e0 < end; e0 += 32) {
            int e = e0 + lane;
            int c = 0; float v = 0.0f;
            if (e < end) { c = g_hh_col[e]; v = g_hh_val[e]; }
            int n = end - e0; if (n > 32) n = 32;
            if (n == 32) {
                #pragma unroll
                for (int k = 0; k < 32; k++) {
                    int   cc = __shfl_sync(0xffffffffu, c, k);
                    float vv = __shfl_sync(0xffffffffu, v, k);
                    float2 d = hsrc[cc * 32 + lane];
                    acc.x += vv * d.x; acc.y += vv * d.y;
                }
            } else {
                for (int k = 0; k < n; k++) {
                    int   cc = __shfl_sync(0xffffffffu, c, k);
                    float vv = __shfl_sync(0xffffffffu, v, k);
                    float2 d = hsrc[cc * 32 + lane];
                    acc.x += vv * d.x; acc.y += vv * d.y;
                }
            }
        }
    }

    float2 r2;
    r2.x = tanhf(acc.x);
    r2.y = tanhf(acc.y);
    reinterpret_cast<float2*>(g_act)[row * 32 + lane] = r2;
}

// block per batch column b: layernorm over H, write h (r,b) and out (b,t,r)
__global__ void __launch_bounds__(1024) k_ln(const float* __restrict__ gamma,
                                             const float* __restrict__ beta,
                                             float* __restrict__ out, int t) {
    int b = blockIdx.x;
    int tid = threadIdx.x;

    float vals[4];
    float sum = 0.0f, sumsq = 0.0f;
    #pragma unroll
    for (int j = 0; j < 4; j++) {
        int r = tid + j * 1024;
        float a = g_act[r * B + b];
        vals[j] = a;
        sum += a;
        sumsq += a * a;
    }

    // block reduce (sum, sumsq)
    __shared__ float ssum[32], ssq[32];
    int lane = tid & 31, wid = tid >> 5;
    #pragma unroll
    for (int off = 16; off > 0; off >>= 1) {
        sum   += __shfl_xor_sync(0xffffffffu, sum, off);
        sumsq += __shfl_xor_sync(0xffffffffu, sumsq, off);
    }
    if (lane == 0) { ssum[wid] = sum; ssq[wid] = sumsq; }
    __syncthreads();
    if (wid == 0) {
        float s = ssum[lane], q = ssq[lane];
        #pragma unroll
        for (int off = 16; off > 0; off >>= 1) {
            s += __shfl_xor_sync(0xffffffffu, s, off);
            q += __shfl_xor_sync(0xffffffffu, q, off);
        }
        if (lane == 0) { ssum[0] = s; ssq[0] = q; }
    }
    __syncthreads();
    float mu  = ssum[0] * (1.0f / (float)H);
    float var = ssq[0] * (1.0f / (float)H) - mu * mu;
    float inv = rsqrtf(var + LN_EPS);

    float* outp = out + ((size_t)b * T + t) * H;
    #pragma unroll
    for (int j = 0; j < 4; j++) {
        int r = tid + j * 1024;
        float hv = (vals[j] - mu) * inv * gamma[r] + beta[r];
        g_h[r * B + b] = hv;    // strided store, small traffic
        outp[r] = hv;           // coalesced
    }
}

__global__ void k_hlast(float* __restrict__ hl) {
    int idx = blockIdx.x * blockDim.x + threadIdx.x;
    int stride = gridDim.x * blockDim.x;
    for (int j = idx; j < B * H; j += stride) {
        int b = j / H, r = j % H;
        hl[j] = g_h[r * B + b];
    }
}

// ---------------- launch ----------------

extern "C" void kernel_launch(void* const* d_in, const int* in_sizes, int n_in,
                              void* d_out, int out_size) {
    const float* x       = (const float*)d_in[0];
    const int*   ih_rows = (const int*)  d_in[1];
    const int*   ih_cols = (const int*)  d_in[2];
    const float* ih_vals = (const float*)d_in[3];
    const int*   hh_rows = (const int*)  d_in[4];
    const int*   hh_cols = (const int*)  d_in[5];
    const float* hh_vals = (const float*)d_in[6];
    const float* b_ih    = (const float*)d_in[7];
    const float* b_hh    = (const float*)d_in[8];
    const float* gamma   = (const float*)d_in[9];
    const float* beta    = (const float*)d_in[10];
    float* out = (float*)d_out;

    // preprocessing: COO -> CSR (counting sort) + x transpose + h0 = 0
    k_init<<<512, 256>>>();
    k_hist<<<1024, 256>>>(ih_rows, hh_rows);
    k_scan<<<1, 1024>>>();
    k_scatter<<<1024, 256>>>(ih_rows, ih_cols, ih_vals, hh_rows, hh_cols, hh_vals);
    k_transpose<<<4096, 256>>>(x);

    // sequential recurrence
    for (int t = 0; t < T; t++) {
        k_spmm<<<512, 256>>>(b_ih, b_hh, t);
        k_ln<<<64, 1024>>>(gamma, beta, out, t);
    }

    if ((size_t)out_size >= (size_t)B * T * H + (size_t)B * H) {
        k_hlast<<<512, 256>>>(out + (size_t)B * T * H);
    }
}